// round 14
// baseline (speedup 1.0000x reference)
#include <cuda_runtime.h>
#include <cuda_fp16.h>
#include <cstdint>

// Problem dims
#define BB 128
#define TT 512
#define II 256
#define HH 512
#define KK 768               // I + H
#define CLU 16

// ---------------- device-global scratch ----------------
__device__ __half g_P[(size_t)BB * TT * 2048];   // preact x·Wx^T + bias, [m=b*512+t][gc]
__device__ uint4  g_WhF2[16 * 8 * 32 * 32];      // 2 MB : Wh B-frags (lstm, reg-resident)
__device__ uint4  g_hf[2 * 8 * 1024];            // h in A-frag order, [parity][group][1024]

// ---------------- helpers ----------------
__device__ __forceinline__ uint32_t smem_u32(const void* p) {
    uint32_t a;
    asm("{ .reg .u64 t; cvta.to.shared.u64 t, %1; cvt.u32.u64 %0, t; }" : "=r"(a) : "l"(p));
    return a;
}
__device__ __forceinline__ uint4 ldcg_v4(const uint4* p) {
    uint4 v;
    asm volatile("ld.global.cg.v4.u32 {%0,%1,%2,%3}, [%4];"
                 : "=r"(v.x), "=r"(v.y), "=r"(v.z), "=r"(v.w) : "l"(p));
    return v;
}
__device__ __forceinline__ void mma16816(float* c, const uint4& a, unsigned b0, unsigned b1) {
    asm volatile(
        "mma.sync.aligned.m16n8k16.row.col.f32.f16.f16.f32 "
        "{%0,%1,%2,%3}, {%4,%5,%6,%7}, {%8,%9}, {%0,%1,%2,%3};"
        : "+f"(c[0]), "+f"(c[1]), "+f"(c[2]), "+f"(c[3])
        : "r"(a.x), "r"(a.y), "r"(a.z), "r"(a.w), "r"(b0), "r"(b1));
}
__device__ __forceinline__ void ldmatrix_x4(uint4& a, uint32_t addr) {
    asm volatile("ldmatrix.sync.aligned.m8n8.x4.shared.b16 {%0,%1,%2,%3}, [%4];"
                 : "=r"(a.x), "=r"(a.y), "=r"(a.z), "=r"(a.w) : "r"(addr));
}
__device__ __forceinline__ float sigf(float x) {
    return __fdividef(1.0f, 1.0f + __expf(-x));
}
__device__ __forceinline__ float tanh_fast(float x) {
    float e = __expf(2.0f * x);
    return 1.0f - __fdividef(2.0f, e + 1.0f);
}

// ---------------- prep kernel: fused [x-GEMM | Wh pack] (unchanged from R11) ----------------
#define PREP_GEMM_BLOCKS 2048
#define PREP_SMEM (2 * 128 * 264 * 2)    // As + Ws, 135168 B

__global__ __launch_bounds__(256) void prep_kernel(
    const float* __restrict__ x,
    const float* __restrict__ Wf, const float* __restrict__ bf,
    const float* __restrict__ Wu, const float* __restrict__ bu,
    const float* __restrict__ Wc, const float* __restrict__ bc,
    const float* __restrict__ Wo, const float* __restrict__ bo) {
    const int tid = threadIdx.x;

    if (blockIdx.x >= PREP_GEMM_BLOCKS) {
        int gid = (blockIdx.x - PREP_GEMM_BLOCKS) * 256 + tid;
        int lane = gid & 31, kt = (gid >> 5) & 31, w = (gid >> 10) & 7, r = (gid >> 13) & 15;
        int gsel = (lane >> 2) & 1;
        int cell = r * 32 + w * 4 + (lane >> 3);
        unsigned* dst = reinterpret_cast<unsigned*>(g_WhF2);
        unsigned base = ((((unsigned)(r * 8 + w) * 32 + kt) * 32 + lane)) * 4;
        #pragma unroll
        for (int q = 0; q < 4; q++) {
            int gate = (q >> 1) * 2 + gsel;
            const float* W = (gate == 0) ? Wf : (gate == 1) ? Wu : (gate == 2) ? Wc : Wo;
            int k2 = (lane & 3) + 4 * (q & 1);
            int kcol = 256 + kt * 16 + k2 * 2;
            __half2 hv = __floats2half2_rn(W[(size_t)cell * KK + kcol],
                                           W[(size_t)cell * KK + kcol + 1]);
            dst[base + q] = *reinterpret_cast<unsigned*>(&hv);
        }
        return;
    }

    extern __shared__ char smem[];
    __half* As = reinterpret_cast<__half*>(smem);
    __half* Ws = As + 128 * 264;
    const int w = tid >> 5, l = tid & 31;
    const int nb = blockIdx.x & 15, grp = blockIdx.x >> 4;

    const int gate = nb >> 2;
    const float* Wg = (gate == 0) ? Wf : (gate == 1) ? Wu : (gate == 2) ? Wc : Wo;
    const float* bias = (gate == 0) ? bf : (gate == 1) ? bu : (gate == 2) ? bc : bo;
    const int col0 = (nb & 3) * 128;

    {
        unsigned* Ws32 = reinterpret_cast<unsigned*>(Ws);
        #pragma unroll 4
        for (int i = 0; i < 32; i++) {
            int idx = tid + i * 256;
            int row = idx >> 6, c4 = idx & 63;
            float4 wv = *reinterpret_cast<const float4*>(
                &Wg[(size_t)(col0 + row) * KK + c4 * 4]);
            __half2 w0 = __floats2half2_rn(wv.x, wv.y);
            __half2 w1 = __floats2half2_rn(wv.z, wv.w);
            Ws32[row * 132 + c4 * 2]     = *reinterpret_cast<unsigned*>(&w0);
            Ws32[row * 132 + c4 * 2 + 1] = *reinterpret_cast<unsigned*>(&w1);
        }
    }

    float bcol[4][2];
    #pragma unroll
    for (int nt = 0; nt < 4; nt++) {
        int cb = col0 + (w & 3) * 32 + nt * 8 + (l & 3) * 2;
        bcol[nt][0] = bias[cb];
        bcol[nt][1] = bias[cb + 1];
    }

    const unsigned* Ws32c = reinterpret_cast<const unsigned*>(Ws);
    const uint32_t a_s = smem_u32(As);
    const int mrow0 = (w >> 2) * 64;
    const int m = l >> 3;

    for (int it = 0; it < 4; it++) {
        const int mb = grp * 4 + it;
        {
            unsigned* As32 = reinterpret_cast<unsigned*>(As);
            #pragma unroll 4
            for (int i = 0; i < 32; i++) {
                int idx = tid + i * 256;
                int row = idx >> 6, c4 = idx & 63;
                float4 v = *reinterpret_cast<const float4*>(
                    &x[((size_t)mb * 128 + row) * 256 + c4 * 4]);
                __half2 h0 = __floats2half2_rn(v.x, v.y);
                __half2 h1 = __floats2half2_rn(v.z, v.w);
                As32[row * 132 + c4 * 2]     = *reinterpret_cast<unsigned*>(&h0);
                As32[row * 132 + c4 * 2 + 1] = *reinterpret_cast<unsigned*>(&h1);
            }
        }
        __syncthreads();

        float acc[4][4][4];
        #pragma unroll
        for (int a = 0; a < 4; a++)
            #pragma unroll
            for (int b = 0; b < 4; b++)
                #pragma unroll
                for (int c = 0; c < 4; c++) acc[a][b][c] = 0.f;

        #pragma unroll 2
        for (int kt = 0; kt < 16; kt++) {
            unsigned bfr[4][2];
            #pragma unroll
            for (int nt = 0; nt < 4; nt++) {
                int colb = ((w & 3) * 4 + nt) * 8 + (l >> 2);
                int base = colb * 132 + kt * 8 + (l & 3);
                bfr[nt][0] = Ws32c[base];
                bfr[nt][1] = Ws32c[base + 4];
            }
            uint4 afr[4];
            #pragma unroll
            for (int mt = 0; mt < 4; mt++) {
                uint32_t addr = a_s +
                    ((mrow0 + mt * 16 + (m & 1) * 8 + (l & 7)) * 264 + kt * 16 + (m >> 1) * 8) * 2;
                ldmatrix_x4(afr[mt], addr);
            }
            #pragma unroll
            for (int mt = 0; mt < 4; mt++)
                #pragma unroll
                for (int nt = 0; nt < 4; nt++)
                    mma16816(acc[mt][nt], afr[mt], bfr[nt][0], bfr[nt][1]);
        }

        #pragma unroll
        for (int mt = 0; mt < 4; mt++) {
            #pragma unroll
            for (int nt = 0; nt < 4; nt++) {
                int mloc = mrow0 + mt * 16 + (l >> 2);
                size_t m0 = (size_t)mb * 128 + mloc;
                int gc = nb * 128 + (w & 3) * 32 + nt * 8 + (l & 3) * 2;
                #pragma unroll
                for (int cp = 0; cp < 2; cp++) {
                    float v0 = acc[mt][nt][cp * 2]     + bcol[nt][0];
                    float v1 = acc[mt][nt][cp * 2 + 1] + bcol[nt][1];
                    __half2 hv = __floats2half2_rn(v0, v1);
                    *reinterpret_cast<unsigned*>(&g_P[(m0 + cp * 8) * 2048 + gc]) =
                        *reinterpret_cast<unsigned*>(&hv);
                }
            }
        }
        __syncthreads();
    }
}

// ---------------- recurrent kernel ----------------
// R11 structure, but the A-operand (h) is read DIRECTLY from g_hf via
// coalesced LDG into a 16-deep register ring feeding the MMAs. Removes the
// SMEM gather, the LDS in the MMA loop, and the pre-MMA __syncthreads.
// Per-step sync: one __syncthreads (publish staging) + one cluster barrier.
#define L_SMEM 1024

__global__ void __cluster_dims__(CLU, 1, 1) __launch_bounds__(256, 1)
lstm_kernel(float* __restrict__ out) {
    extern __shared__ char smem[];
    __half* sStage = reinterpret_cast<__half*>(smem);        // 512 halves staging

    const int tid  = threadIdx.x;
    const int w    = tid >> 5;
    const int lane = tid & 31;
    const int r    = blockIdx.x & (CLU - 1);
    const int bgrp = blockIdx.x >> 4;
    const int bb   = bgrp * 16;
    const int hb   = r * 32;

    // ---- weights into registers (once) ----
    uint4 wb_[32];
    {
        const uint4* src = g_WhF2 + ((size_t)(r * 8 + w) * 32) * 32;
        #pragma unroll
        for (int kt = 0; kt < 32; kt++) wb_[kt] = src[kt * 32 + lane];
    }

    // ---- per-thread ownership: rows {rA, rA+8}, cell hg ----
    const int rA = lane >> 2;
    const int hg = hb + w * 4 + (lane & 3);
    const int c  = w * 4 + (lane & 3);           // local cell index 0..31
    const int stg0 = ((c >> 4) * 32 + rA * 4 + ((c >> 1) & 3)) * 8
                     + ((c >> 3) & 1) * 4 + (c & 1);

    float cs0 = 0.f, cs1 = 0.f, hv0 = 0.f, hv1 = 0.f;

    const __half* P0 = g_P + ((size_t)(bb + rA) * 512) * 2048;
    const __half* P8 = g_P + ((size_t)(bb + rA + 8) * 512) * 2048;

    float pv[8];
    {
        pv[0] = __half2float(__ldg(P0 + hg));
        pv[1] = __half2float(__ldg(P0 + 512 + hg));
        pv[2] = __half2float(__ldg(P8 + hg));
        pv[3] = __half2float(__ldg(P8 + 512 + hg));
        pv[4] = __half2float(__ldg(P0 + 1024 + hg));
        pv[5] = __half2float(__ldg(P0 + 1536 + hg));
        pv[6] = __half2float(__ldg(P8 + 1024 + hg));
        pv[7] = __half2float(__ldg(P8 + 1536 + hg));
    }

    for (int t = 0; t < TT; t++) {
        // ---- 4 independent accumulator chains, seeded with P(t) ----
        float a0e[4] = {pv[0], pv[1], pv[2], pv[3]};
        float a1e[4] = {pv[4], pv[5], pv[6], pv[7]};
        float a0o[4] = {0.f, 0.f, 0.f, 0.f};
        float a1o[4] = {0.f, 0.f, 0.f, 0.f};

        // ---- GEMM: 16 x 128 x 512; A direct from L2 via 16-deep LDG ring ----
        // h(0) = 0 -> contribution zero -> skip the MMA loop entirely at t=0.
        if (t > 0) {
            const uint4* hf = g_hf + ((size_t)(t & 1) * 8 + bgrp) * 1024;
            uint4 Areg[16];
            #pragma unroll
            for (int i = 0; i < 16; i++) Areg[i] = ldcg_v4(hf + i * 32 + lane);
            #pragma unroll
            for (int kt = 0; kt < 32; kt++) {
                uint4 A = Areg[kt & 15];
                if (kt < 16) Areg[kt & 15] = ldcg_v4(hf + (kt + 16) * 32 + lane);
                if (kt & 1) {
                    mma16816(a0o, A, wb_[kt].x, wb_[kt].y);
                    mma16816(a1o, A, wb_[kt].z, wb_[kt].w);
                } else {
                    mma16816(a0e, A, wb_[kt].x, wb_[kt].y);
                    mma16816(a1e, A, wb_[kt].z, wb_[kt].w);
                }
            }
        }

        // ---- merge chains + epilogue: 2 cells ----
        {
            float f, u, g, o;
            f = sigf(a0e[0] + a0o[0]); u = sigf(a0e[1] + a0o[1]);
            g = tanh_fast(a1e[0] + a1o[0]); o = sigf(a1e[1] + a1o[1]);
            cs0 = f * cs0 + u * g;  hv0 = o * tanh_fast(cs0);
            f = sigf(a0e[2] + a0o[2]); u = sigf(a0e[3] + a0o[3]);
            g = tanh_fast(a1e[2] + a1o[2]); o = sigf(a1e[3] + a1o[3]);
            cs1 = f * cs1 + u * g;  hv1 = o * tanh_fast(cs1);
        }

        // ---- stage h(t+1) in SMEM (A-frag order) ----
        sStage[stg0]     = __float2half(hv0);
        sStage[stg0 + 2] = __float2half(hv1);
        __syncthreads();

        // ---- coalesced publish: 64 x STG.128 (2 cache lines) ----
        if (tid < 64) {
            const int wb2 = (t + 1) & 1;
            uint4 v = reinterpret_cast<const uint4*>(sStage)[tid];
            g_hf[(size_t)(wb2 * 8 + bgrp) * 1024 + r * 64 + tid] = v;
        }

        asm volatile("barrier.cluster.arrive.release.aligned;" ::: "memory");

        // ---- under the barrier wait: out stores + P(t+1) prefetch ----
        out[(size_t)t * (BB * HH) + (size_t)(bb + rA) * HH + hg] = hv0;
        out[(size_t)t * (BB * HH) + (size_t)(bb + rA + 8) * HH + hg] = hv1;
        if (t + 1 < TT) {
            const __half* p0 = P0 + (size_t)(t + 1) * 2048;
            const __half* p8 = P8 + (size_t)(t + 1) * 2048;
            pv[0] = __half2float(__ldg(p0 + hg));
            pv[1] = __half2float(__ldg(p0 + 512 + hg));
            pv[2] = __half2float(__ldg(p8 + hg));
            pv[3] = __half2float(__ldg(p8 + 512 + hg));
            pv[4] = __half2float(__ldg(p0 + 1024 + hg));
            pv[5] = __half2float(__ldg(p0 + 1536 + hg));
            pv[6] = __half2float(__ldg(p8 + 1024 + hg));
            pv[7] = __half2float(__ldg(p8 + 1536 + hg));
        }

        asm volatile("barrier.cluster.wait.acquire.aligned;" ::: "memory");
        __syncthreads();   // all threads past wait before next staging write
    }

    // ---- final h, c ----
    {
        const size_t OUT_H = (size_t)TT * BB * HH;
        const size_t OUT_C = OUT_H + (size_t)BB * HH;
        size_t b0 = (size_t)(bb + rA) * HH + hg;
        size_t b1 = (size_t)(bb + rA + 8) * HH + hg;
        out[OUT_H + b0] = hv0;  out[OUT_H + b1] = hv1;
        out[OUT_C + b0] = cs0;  out[OUT_C + b1] = cs1;
    }
}

// ---------------- launcher (2 launches: lstm profiled at global index 3) ----------------

extern "C" void kernel_launch(void* const* d_in, const int* in_sizes, int n_in,
                              void* d_out, int out_size) {
    (void)in_sizes; (void)n_in; (void)out_size;
    const float* x  = (const float*)d_in[0];
    const float* Wf = (const float*)d_in[1];
    const float* bf = (const float*)d_in[2];
    const float* Wu = (const float*)d_in[3];
    const float* bu = (const float*)d_in[4];
    const float* Wc = (const float*)d_in[5];
    const float* bc = (const float*)d_in[6];
    const float* Wo = (const float*)d_in[7];
    const float* bo = (const float*)d_in[8];
    float* out = (float*)d_out;

    cudaFuncSetAttribute(prep_kernel, cudaFuncAttributeMaxDynamicSharedMemorySize, PREP_SMEM);
    cudaFuncSetAttribute(lstm_kernel, cudaFuncAttributeMaxDynamicSharedMemorySize, L_SMEM);
    cudaFuncSetAttribute(lstm_kernel, cudaFuncAttributeNonPortableClusterSizeAllowed, 1);

    prep_kernel<<<PREP_GEMM_BLOCKS + 512, 256, PREP_SMEM>>>(x, Wf, bf, Wu, bu, Wc, bc, Wo, bo);
    lstm_kernel<<<BB, 256, L_SMEM>>>(out);
}

// round 15
// speedup vs baseline: 1.3741x; 1.3741x over previous
#include <cuda_runtime.h>
#include <cuda_fp16.h>
#include <cstdint>

// Problem dims
#define BB 128
#define TT 512
#define II 256
#define HH 512
#define KK 768               // I + H
#define CLU 16

// ---------------- device-global scratch ----------------
__device__ __half g_P[(size_t)BB * TT * 2048];   // preact x·Wx^T + bias, [m=b*512+t][gc]
__device__ uint4  g_WhF2[16 * 8 * 32 * 32];      // 2 MB : Wh B-frags (lstm, reg-resident)
__device__ uint4  g_hf[2 * 8 * 1024];            // h in A-frag order, [parity][group][1024]

// ---------------- helpers ----------------
__device__ __forceinline__ uint32_t smem_u32(const void* p) {
    uint32_t a;
    asm("{ .reg .u64 t; cvta.to.shared.u64 t, %1; cvt.u32.u64 %0, t; }" : "=r"(a) : "l"(p));
    return a;
}
__device__ __forceinline__ uint4 ldcg_v4(const uint4* p) {
    uint4 v;
    asm volatile("ld.global.cg.v4.u32 {%0,%1,%2,%3}, [%4];"
                 : "=r"(v.x), "=r"(v.y), "=r"(v.z), "=r"(v.w) : "l"(p));
    return v;
}
__device__ __forceinline__ void mma16816(float* c, const uint4& a, unsigned b0, unsigned b1) {
    asm volatile(
        "mma.sync.aligned.m16n8k16.row.col.f32.f16.f16.f32 "
        "{%0,%1,%2,%3}, {%4,%5,%6,%7}, {%8,%9}, {%0,%1,%2,%3};"
        : "+f"(c[0]), "+f"(c[1]), "+f"(c[2]), "+f"(c[3])
        : "r"(a.x), "r"(a.y), "r"(a.z), "r"(a.w), "r"(b0), "r"(b1));
}
__device__ __forceinline__ void ldmatrix_x4(uint4& a, uint32_t addr) {
    asm volatile("ldmatrix.sync.aligned.m8n8.x4.shared.b16 {%0,%1,%2,%3}, [%4];"
                 : "=r"(a.x), "=r"(a.y), "=r"(a.z), "=r"(a.w) : "r"(addr));
}
__device__ __forceinline__ float sigf(float x) {
    return __fdividef(1.0f, 1.0f + __expf(-x));
}
__device__ __forceinline__ float tanh_fast(float x) {
    float e = __expf(2.0f * x);
    return 1.0f - __fdividef(2.0f, e + 1.0f);
}

// ---------------- prep kernel: fused [x-GEMM | Wh pack] ----------------
// Blocks 0..2047: gemm (nb = bid&15, grp = bid>>4). Block converts its fp32 W
//   slice to fp16 SMEM once, then sweeps EIGHT 64-row M-subtiles against it.
//   SMEM 101 KB -> 2 CTAs/SM: co-resident blocks overlap load/convert with MMA.
// Blocks 2048..2559: pack Wh -> g_WhF2 (lstm's register-resident B-frags).
#define PREP_GEMM_BLOCKS 2048
#define PREP_SMEM (64 * 264 * 2 + 128 * 264 * 2)   // As(64 rows) + Ws = 101376 B

__global__ __launch_bounds__(256) void prep_kernel(
    const float* __restrict__ x,
    const float* __restrict__ Wf, const float* __restrict__ bf,
    const float* __restrict__ Wu, const float* __restrict__ bu,
    const float* __restrict__ Wc, const float* __restrict__ bc,
    const float* __restrict__ Wo, const float* __restrict__ bo) {
    const int tid = threadIdx.x;

    if (blockIdx.x >= PREP_GEMM_BLOCKS) {
        int gid = (blockIdx.x - PREP_GEMM_BLOCKS) * 256 + tid;
        int lane = gid & 31, kt = (gid >> 5) & 31, w = (gid >> 10) & 7, r = (gid >> 13) & 15;
        int gsel = (lane >> 2) & 1;
        int cell = r * 32 + w * 4 + (lane >> 3);
        unsigned* dst = reinterpret_cast<unsigned*>(g_WhF2);
        unsigned base = ((((unsigned)(r * 8 + w) * 32 + kt) * 32 + lane)) * 4;
        #pragma unroll
        for (int q = 0; q < 4; q++) {
            int gate = (q >> 1) * 2 + gsel;
            const float* W = (gate == 0) ? Wf : (gate == 1) ? Wu : (gate == 2) ? Wc : Wo;
            int k2 = (lane & 3) + 4 * (q & 1);
            int kcol = 256 + kt * 16 + k2 * 2;
            __half2 hv = __floats2half2_rn(W[(size_t)cell * KK + kcol],
                                           W[(size_t)cell * KK + kcol + 1]);
            dst[base + q] = *reinterpret_cast<unsigned*>(&hv);
        }
        return;
    }

    extern __shared__ char smem[];
    __half* As = reinterpret_cast<__half*>(smem);            // [64 rows][264]
    __half* Ws = As + 64 * 264;                              // [128 cols][264]
    const int w = tid >> 5, l = tid & 31;
    const int nb = blockIdx.x & 15, grp = blockIdx.x >> 4;   // grp 0..127

    const int gate = nb >> 2;
    const float* Wg = (gate == 0) ? Wf : (gate == 1) ? Wu : (gate == 2) ? Wc : Wo;
    const float* bias = (gate == 0) ? bf : (gate == 1) ? bu : (gate == 2) ? bc : bo;
    const int col0 = (nb & 3) * 128;

    // convert W slice fp32 -> fp16 SMEM (once per block)
    {
        unsigned* Ws32 = reinterpret_cast<unsigned*>(Ws);
        #pragma unroll 4
        for (int i = 0; i < 32; i++) {
            int idx = tid + i * 256;
            int row = idx >> 6, c4 = idx & 63;
            float4 wv = *reinterpret_cast<const float4*>(
                &Wg[(size_t)(col0 + row) * KK + c4 * 4]);
            __half2 w0 = __floats2half2_rn(wv.x, wv.y);
            __half2 w1 = __floats2half2_rn(wv.z, wv.w);
            Ws32[row * 132 + c4 * 2]     = *reinterpret_cast<unsigned*>(&w0);
            Ws32[row * 132 + c4 * 2 + 1] = *reinterpret_cast<unsigned*>(&w1);
        }
    }

    float bcol[4][2];
    #pragma unroll
    for (int nt = 0; nt < 4; nt++) {
        int cb = col0 + (w & 3) * 32 + nt * 8 + (l & 3) * 2;
        bcol[nt][0] = bias[cb];
        bcol[nt][1] = bias[cb + 1];
    }

    const unsigned* Ws32c = reinterpret_cast<const unsigned*>(Ws);
    const uint32_t a_s = smem_u32(As);
    const int mrow0 = (w >> 2) * 32;          // two 32-row halves across warp groups
    const int m = l >> 3;

    for (int it = 0; it < 8; it++) {
        const int mb64 = grp * 8 + it;        // 64-row M-subtile index (0..1023)

        // load A subtile (x, 64 rows) fp32 -> fp16 SMEM
        {
            unsigned* As32 = reinterpret_cast<unsigned*>(As);
            #pragma unroll 4
            for (int i = 0; i < 16; i++) {
                int idx = tid + i * 256;
                int row = idx >> 6, c4 = idx & 63;
                float4 v = *reinterpret_cast<const float4*>(
                    &x[((size_t)mb64 * 64 + row) * 256 + c4 * 4]);
                __half2 h0 = __floats2half2_rn(v.x, v.y);
                __half2 h1 = __floats2half2_rn(v.z, v.w);
                As32[row * 132 + c4 * 2]     = *reinterpret_cast<unsigned*>(&h0);
                As32[row * 132 + c4 * 2 + 1] = *reinterpret_cast<unsigned*>(&h1);
            }
        }
        __syncthreads();

        float acc[2][4][4];
        #pragma unroll
        for (int a = 0; a < 2; a++)
            #pragma unroll
            for (int b = 0; b < 4; b++)
                #pragma unroll
                for (int c = 0; c < 4; c++) acc[a][b][c] = 0.f;

        #pragma unroll 2
        for (int kt = 0; kt < 16; kt++) {
            unsigned bfr[4][2];
            #pragma unroll
            for (int nt = 0; nt < 4; nt++) {
                int colb = ((w & 3) * 4 + nt) * 8 + (l >> 2);
                int base = colb * 132 + kt * 8 + (l & 3);
                bfr[nt][0] = Ws32c[base];
                bfr[nt][1] = Ws32c[base + 4];
            }
            uint4 afr[2];
            #pragma unroll
            for (int mt = 0; mt < 2; mt++) {
                uint32_t addr = a_s +
                    ((mrow0 + mt * 16 + (m & 1) * 8 + (l & 7)) * 264 + kt * 16 + (m >> 1) * 8) * 2;
                ldmatrix_x4(afr[mt], addr);
            }
            #pragma unroll
            for (int mt = 0; mt < 2; mt++)
                #pragma unroll
                for (int nt = 0; nt < 4; nt++)
                    mma16816(acc[mt][nt], afr[mt], bfr[nt][0], bfr[nt][1]);
        }

        // epilogue: +bias, fp16, store P
        #pragma unroll
        for (int mt = 0; mt < 2; mt++) {
            #pragma unroll
            for (int nt = 0; nt < 4; nt++) {
                int mloc = mrow0 + mt * 16 + (l >> 2);
                size_t m0 = (size_t)mb64 * 64 + mloc;
                int gc = nb * 128 + (w & 3) * 32 + nt * 8 + (l & 3) * 2;
                #pragma unroll
                for (int cp = 0; cp < 2; cp++) {
                    float v0 = acc[mt][nt][cp * 2]     + bcol[nt][0];
                    float v1 = acc[mt][nt][cp * 2 + 1] + bcol[nt][1];
                    __half2 hv = __floats2half2_rn(v0, v1);
                    *reinterpret_cast<unsigned*>(&g_P[(m0 + cp * 8) * 2048 + gc]) =
                        *reinterpret_cast<unsigned*>(&hv);
                }
            }
        }
        __syncthreads();   // As consumed; safe to reload next it
    }
}

// ---------------- recurrent kernel (byte-identical to R11 = proven 2378) ----------------
#define L_SMEM (16384 + 1024)

__global__ void __cluster_dims__(CLU, 1, 1) __launch_bounds__(256, 1)
lstm_kernel(float* __restrict__ out) {
    extern __shared__ char smem[];
    uint4* sA = reinterpret_cast<uint4*>(smem);                      // 1024 uint4 = h A-frags
    __half* sStage = reinterpret_cast<__half*>(smem + 16384);        // 512 halves staging

    const int tid  = threadIdx.x;
    const int w    = tid >> 5;
    const int lane = tid & 31;
    const int r    = blockIdx.x & (CLU - 1);
    const int bgrp = blockIdx.x >> 4;
    const int bb   = bgrp * 16;
    const int hb   = r * 32;

    // ---- weights into registers (once) ----
    uint4 wb_[32];
    {
        const uint4* src = g_WhF2 + ((size_t)(r * 8 + w) * 32) * 32;
        #pragma unroll
        for (int kt = 0; kt < 32; kt++) wb_[kt] = src[kt * 32 + lane];
    }

    // ---- per-thread ownership: rows {rA, rA+8}, cell hg ----
    const int rA = lane >> 2;
    const int hg = hb + w * 4 + (lane & 3);
    const int c  = w * 4 + (lane & 3);           // local cell index 0..31
    const int stg0 = ((c >> 4) * 32 + rA * 4 + ((c >> 1) & 3)) * 8
                     + ((c >> 3) & 1) * 4 + (c & 1);

    float cs0 = 0.f, cs1 = 0.f, hv0 = 0.f, hv1 = 0.f;

    const __half* P0 = g_P + ((size_t)(bb + rA) * 512) * 2048;
    const __half* P8 = g_P + ((size_t)(bb + rA + 8) * 512) * 2048;

    float pv[8];
    {
        pv[0] = __half2float(__ldg(P0 + hg));
        pv[1] = __half2float(__ldg(P0 + 512 + hg));
        pv[2] = __half2float(__ldg(P8 + hg));
        pv[3] = __half2float(__ldg(P8 + 512 + hg));
        pv[4] = __half2float(__ldg(P0 + 1024 + hg));
        pv[5] = __half2float(__ldg(P0 + 1536 + hg));
        pv[6] = __half2float(__ldg(P8 + 1024 + hg));
        pv[7] = __half2float(__ldg(P8 + 1536 + hg));
    }

    for (int t = 0; t < TT; t++) {
        // ---- stage A frags: h(t) from g_hf (frag order), zeros at t=0 ----
        if (t == 0) {
            uint4 z = make_uint4(0, 0, 0, 0);
            #pragma unroll
            for (int i = 0; i < 4; i++) sA[tid + i * 256] = z;
        } else {
            const uint4* hf = g_hf + ((size_t)(t & 1) * 8 + bgrp) * 1024;
            #pragma unroll
            for (int i = 0; i < 4; i++) sA[tid + i * 256] = ldcg_v4(hf + tid + i * 256);
        }
        __syncthreads();

        // ---- 4 independent accumulator chains, seeded with P(t) ----
        float a0e[4] = {pv[0], pv[1], pv[2], pv[3]};
        float a1e[4] = {pv[4], pv[5], pv[6], pv[7]};
        float a0o[4] = {0.f, 0.f, 0.f, 0.f};
        float a1o[4] = {0.f, 0.f, 0.f, 0.f};

        // ---- GEMM: 16 x 128 x 512, B in registers, pipelined A LDS ----
        uint4 Acur = sA[lane];
        #pragma unroll
        for (int kt = 0; kt < 32; kt++) {
            uint4 Anext;
            if (kt < 31) Anext = sA[(kt + 1) * 32 + lane];
            if (kt & 1) {
                mma16816(a0o, Acur, wb_[kt].x, wb_[kt].y);
                mma16816(a1o, Acur, wb_[kt].z, wb_[kt].w);
            } else {
                mma16816(a0e, Acur, wb_[kt].x, wb_[kt].y);
                mma16816(a1e, Acur, wb_[kt].z, wb_[kt].w);
            }
            Acur = Anext;
        }

        // ---- merge chains + epilogue: 2 cells ----
        {
            float f, u, g, o;
            f = sigf(a0e[0] + a0o[0]); u = sigf(a0e[1] + a0o[1]);
            g = tanh_fast(a1e[0] + a1o[0]); o = sigf(a1e[1] + a1o[1]);
            cs0 = f * cs0 + u * g;  hv0 = o * tanh_fast(cs0);
            f = sigf(a0e[2] + a0o[2]); u = sigf(a0e[3] + a0o[3]);
            g = tanh_fast(a1e[2] + a1o[2]); o = sigf(a1e[3] + a1o[3]);
            cs1 = f * cs1 + u * g;  hv1 = o * tanh_fast(cs1);
        }

        // ---- stage h(t+1) in SMEM (A-frag order) ----
        sStage[stg0]     = __float2half(hv0);
        sStage[stg0 + 2] = __float2half(hv1);
        __syncthreads();

        // ---- coalesced publish: 64 x STG.128 (2 cache lines) ----
        if (tid < 64) {
            const int wb2 = (t + 1) & 1;
            uint4 v = reinterpret_cast<const uint4*>(sStage)[tid];
            g_hf[(size_t)(wb2 * 8 + bgrp) * 1024 + r * 64 + tid] = v;
        }

        asm volatile("barrier.cluster.arrive.release.aligned;" ::: "memory");

        // ---- under the barrier wait: out stores + P(t+1) prefetch ----
        out[(size_t)t * (BB * HH) + (size_t)(bb + rA) * HH + hg] = hv0;
        out[(size_t)t * (BB * HH) + (size_t)(bb + rA + 8) * HH + hg] = hv1;
        if (t + 1 < TT) {
            const __half* p0 = P0 + (size_t)(t + 1) * 2048;
            const __half* p8 = P8 + (size_t)(t + 1) * 2048;
            pv[0] = __half2float(__ldg(p0 + hg));
            pv[1] = __half2float(__ldg(p0 + 512 + hg));
            pv[2] = __half2float(__ldg(p8 + hg));
            pv[3] = __half2float(__ldg(p8 + 512 + hg));
            pv[4] = __half2float(__ldg(p0 + 1024 + hg));
            pv[5] = __half2float(__ldg(p0 + 1536 + hg));
            pv[6] = __half2float(__ldg(p8 + 1024 + hg));
            pv[7] = __half2float(__ldg(p8 + 1536 + hg));
        }

        asm volatile("barrier.cluster.wait.acquire.aligned;" ::: "memory");
    }

    // ---- final h, c ----
    {
        const size_t OUT_H = (size_t)TT * BB * HH;
        const size_t OUT_C = OUT_H + (size_t)BB * HH;
        size_t b0 = (size_t)(bb + rA) * HH + hg;
        size_t b1 = (size_t)(bb + rA + 8) * HH + hg;
        out[OUT_H + b0] = hv0;  out[OUT_H + b1] = hv1;
        out[OUT_C + b0] = cs0;  out[OUT_C + b1] = cs1;
    }
}

// ---------------- launcher (2 launches: lstm profiled at global index 3) ----------------

extern "C" void kernel_launch(void* const* d_in, const int* in_sizes, int n_in,
                              void* d_out, int out_size) {
    (void)in_sizes; (void)n_in; (void)out_size;
    const float* x  = (const float*)d_in[0];
    const float* Wf = (const float*)d_in[1];
    const float* bf = (const float*)d_in[2];
    const float* Wu = (const float*)d_in[3];
    const float* bu = (const float*)d_in[4];
    const float* Wc = (const float*)d_in[5];
    const float* bc = (const float*)d_in[6];
    const float* Wo = (const float*)d_in[7];
    const float* bo = (const float*)d_in[8];
    float* out = (float*)d_out;

    cudaFuncSetAttribute(prep_kernel, cudaFuncAttributeMaxDynamicSharedMemorySize, PREP_SMEM);
    cudaFuncSetAttribute(lstm_kernel, cudaFuncAttributeMaxDynamicSharedMemorySize, L_SMEM);
    cudaFuncSetAttribute(lstm_kernel, cudaFuncAttributeNonPortableClusterSizeAllowed, 1);

    prep_kernel<<<PREP_GEMM_BLOCKS + 512, 256, PREP_SMEM>>>(x, Wf, bf, Wu, bu, Wc, bc, Wo, bo);
    lstm_kernel<<<BB, 256, L_SMEM>>>(out);
}